// round 1
// baseline (speedup 1.0000x reference)
#include <cuda_runtime.h>

// Problem: B=8, C=512, H=W=64, P=H*W=4096
// out[b,c,h,w] = f_opt*f_sar*had^2, had = softmax_c(S_opt)*softmax_c(S_sar)
// f = W @ x (per-pixel channel mix), S[b,c] = f_bc^T f_bc (64x64)

#define NB 8
#define NC 512
#define NP 4096          // 64*64
#define BR_STRIDE ((size_t)NB * NC * NP)   // floats per branch = 16,777,216

// Scratch (static device arrays; no allocation allowed)
__device__ float g_f[2ull * NB * NC * NP];   // 134 MB
__device__ float g_S[2ull * NB * NC * NP];   // 134 MB
__device__ float g_m[2 * NB * NP];           // per-(br,b,i,j) softmax max
__device__ float g_z[2 * NB * NP];           // per-(br,b,i,j) softmax sum

// ---- packed f32x2 helpers (FFMA2 — only reachable via PTX) ----
__device__ __forceinline__ unsigned long long pk2(float x, float y) {
    unsigned long long r;
    asm("mov.b64 %0, {%1,%2};" : "=l"(r) : "f"(x), "f"(y));
    return r;
}
__device__ __forceinline__ void fma2(unsigned long long& d, unsigned long long a, unsigned long long b) {
    asm("fma.rn.f32x2 %0, %1, %2, %0;" : "+l"(d) : "l"(a), "l"(b));
}
__device__ __forceinline__ float2 up2(unsigned long long v) {
    float2 r;
    asm("mov.b64 {%0,%1}, %2;" : "=f"(r.x), "=f"(r.y) : "l"(v));
    return r;
}

// ============================================================================
// K1: f[br][b] = W_br (512x512) @ x[b] (512x4096)
// Tiles: BM=128, BN=128, BK=16; 256 threads; 8x8 per thread via f32x2.
// grid = (4096/128=32, 512/128=4, 16 (br*8+b))
// ============================================================================
__global__ __launch_bounds__(256, 2) void k1_gemm(
    const float* __restrict__ opt, const float* __restrict__ sar,
    const float* __restrict__ Wo, const float* __restrict__ Ws)
{
    const int z = blockIdx.z;
    const int br = z >> 3, b = z & 7;
    const float* X = (br ? sar : opt) + (size_t)b * NC * NP;
    const float* A = br ? Ws : Wo;
    float* Cg = g_f + (size_t)z * NC * NP;

    __shared__ float As[16][132];   // transposed A tile, padded
    __shared__ float Bs[16][128];

    const int tid = threadIdx.x;
    const int tx = tid & 15, ty = tid >> 4;
    const int row0 = blockIdx.y * 128;
    const int col0 = blockIdx.x * 128;

    unsigned long long acc[4][8];
#pragma unroll
    for (int q = 0; q < 4; q++)
#pragma unroll
        for (int j = 0; j < 8; j++) acc[q][j] = 0ull;

    for (int kt = 0; kt < NC / 16; kt++) {
#pragma unroll
        for (int it = 0; it < 2; it++) {
            int f4 = tid + it * 256;
            // A tile: 128 rows x 16 cols (4 float4/row)
            int r = f4 >> 2, c4 = f4 & 3;
            float4 v = *(const float4*)(A + (size_t)(row0 + r) * NC + kt * 16 + c4 * 4);
            As[c4 * 4 + 0][r] = v.x;
            As[c4 * 4 + 1][r] = v.y;
            As[c4 * 4 + 2][r] = v.z;
            As[c4 * 4 + 3][r] = v.w;
            // B tile: 16 rows x 128 cols (32 float4/row)
            int rB = f4 >> 5, cB = (f4 & 31) * 4;
            *(float4*)&Bs[rB][cB] =
                *(const float4*)(X + (size_t)(kt * 16 + rB) * NP + col0 + cB);
        }
        __syncthreads();

#pragma unroll
        for (int k = 0; k < 16; k++) {
            unsigned long long a2[4];
#pragma unroll
            for (int q = 0; q < 4; q++)
                a2[q] = *(const unsigned long long*)&As[k][ty * 8 + q * 2];
            float4 b0 = *(const float4*)&Bs[k][tx * 8];
            float4 b1 = *(const float4*)&Bs[k][tx * 8 + 4];
            unsigned long long s[8];
            s[0] = pk2(b0.x, b0.x); s[1] = pk2(b0.y, b0.y);
            s[2] = pk2(b0.z, b0.z); s[3] = pk2(b0.w, b0.w);
            s[4] = pk2(b1.x, b1.x); s[5] = pk2(b1.y, b1.y);
            s[6] = pk2(b1.z, b1.z); s[7] = pk2(b1.w, b1.w);
#pragma unroll
            for (int q = 0; q < 4; q++)
#pragma unroll
                for (int j = 0; j < 8; j++) fma2(acc[q][j], a2[q], s[j]);
        }
        __syncthreads();
    }

    // epilogue: rows row0+ty*8+{2q,2q+1}, cols col0+tx*8..+7
#pragma unroll
    for (int q = 0; q < 4; q++) {
        float2 v[8];
#pragma unroll
        for (int j = 0; j < 8; j++) v[j] = up2(acc[q][j]);
        size_t base = (size_t)(row0 + ty * 8 + q * 2) * NP + col0 + tx * 8;
        *(float4*)(Cg + base)          = make_float4(v[0].x, v[1].x, v[2].x, v[3].x);
        *(float4*)(Cg + base + 4)      = make_float4(v[4].x, v[5].x, v[6].x, v[7].x);
        *(float4*)(Cg + base + NP)     = make_float4(v[0].y, v[1].y, v[2].y, v[3].y);
        *(float4*)(Cg + base + NP + 4) = make_float4(v[4].y, v[5].y, v[6].y, v[7].y);
    }
}

// ============================================================================
// K2: S[b,c] = F^T F where F = f[br,b,c] viewed as 64(h) x 64(w), contiguous.
// One block per (br,b,c): 8192 blocks, 256 threads, 4x4 outputs per thread.
// ============================================================================
__global__ __launch_bounds__(256) void k2_gram()
{
    const int blk = blockIdx.x;                    // br*4096 + b*512 + c
    const float* F = g_f + (size_t)blk * NP;
    float* S = g_S + (size_t)blk * NP;

    __shared__ float Fs[64][64];
    const int tid = threadIdx.x;
#pragma unroll
    for (int it = 0; it < 4; it++)
        ((float4*)&Fs[0][0])[tid + it * 256] = ((const float4*)F)[tid + it * 256];
    __syncthreads();

    const int tj = tid & 15, ti = tid >> 4;
    unsigned long long acc[2][4];
#pragma unroll
    for (int p = 0; p < 2; p++)
#pragma unroll
        for (int j = 0; j < 4; j++) acc[p][j] = 0ull;

#pragma unroll 16
    for (int h = 0; h < 64; h++) {
        unsigned long long a0 = *(const unsigned long long*)&Fs[h][ti * 4];
        unsigned long long a1 = *(const unsigned long long*)&Fs[h][ti * 4 + 2];
        float4 bv = *(const float4*)&Fs[h][tj * 4];
        unsigned long long s0 = pk2(bv.x, bv.x), s1 = pk2(bv.y, bv.y);
        unsigned long long s2 = pk2(bv.z, bv.z), s3 = pk2(bv.w, bv.w);
        fma2(acc[0][0], a0, s0); fma2(acc[0][1], a0, s1);
        fma2(acc[0][2], a0, s2); fma2(acc[0][3], a0, s3);
        fma2(acc[1][0], a1, s0); fma2(acc[1][1], a1, s1);
        fma2(acc[1][2], a1, s2); fma2(acc[1][3], a1, s3);
    }

#pragma unroll
    for (int p = 0; p < 2; p++) {
        float2 v0 = up2(acc[p][0]), v1 = up2(acc[p][1]);
        float2 v2 = up2(acc[p][2]), v3 = up2(acc[p][3]);
        *(float4*)&S[(ti * 4 + p * 2) * 64 + tj * 4]     = make_float4(v0.x, v1.x, v2.x, v3.x);
        *(float4*)&S[(ti * 4 + p * 2 + 1) * 64 + tj * 4] = make_float4(v0.y, v1.y, v2.y, v3.y);
    }
}

// ============================================================================
// K3: softmax stats over channel axis for both branches.
// Block per (b,i): 512 blocks, 256 threads = 64 j x 4 c-groups. Online max/sum.
// ============================================================================
__global__ __launch_bounds__(256) void k3_stats()
{
    const int blk = blockIdx.x;
    const int b = blk >> 6, i = blk & 63;
    const int tid = threadIdx.x, j = tid & 63, cg = tid >> 6;

    const float* So = g_S + (size_t)b * NC * NP + i * 64 + j;
    const float* Ss = So + BR_STRIDE;

    float mo = -1e30f, zo = 0.f, ms = -1e30f, zs = 0.f;
    for (int c = cg * 128; c < cg * 128 + 128; c++) {
        float v = So[(size_t)c * NP];
        if (v > mo) { zo = zo * __expf(mo - v) + 1.f; mo = v; }
        else        { zo += __expf(v - mo); }
        float w = Ss[(size_t)c * NP];
        if (w > ms) { zs = zs * __expf(ms - w) + 1.f; ms = w; }
        else        { zs += __expf(w - ms); }
    }

    __shared__ float shm[2][4][64], shz[2][4][64];
    shm[0][cg][j] = mo; shz[0][cg][j] = zo;
    shm[1][cg][j] = ms; shz[1][cg][j] = zs;
    __syncthreads();

    if (cg < 2) {
        const int brn = cg;
        float M = shm[brn][0][j];
#pragma unroll
        for (int q = 1; q < 4; q++) M = fmaxf(M, shm[brn][q][j]);
        float Z = 0.f;
#pragma unroll
        for (int q = 0; q < 4; q++) Z += shz[brn][q][j] * __expf(shm[brn][q][j] - M);
        const int idx = brn * NB * NP + b * NP + i * 64 + j;
        g_m[idx] = M;
        g_z[idx] = Z;
    }
}

// ============================================================================
// K4: out = f_opt*f_sar*had^2, had = exp((So-mo)+(Ss-ms)) / (zo*zs)
// Fully coalesced float4 elementwise. 4,194,304 float4s.
// ============================================================================
__global__ __launch_bounds__(256) void k4_final(float* __restrict__ out)
{
    const int t = blockIdx.x * 256 + threadIdx.x;   // float4 index within branch array
    const int j4 = t & 15;
    const int i = (t >> 4) & 63;
    const int rest = t >> 10;
    const int b = rest >> 9;

    const float4 a  = ((const float4*)g_S)[t];
    const float4 bb = ((const float4*)g_S)[t + (int)(BR_STRIDE / 4)];
    const float4 fo = ((const float4*)g_f)[t];
    const float4 fs = ((const float4*)g_f)[t + (int)(BR_STRIDE / 4)];

    const int mi = b * (NP / 4) + i * 16 + j4;           // float4 index into g_m/g_z
    const float4 mo = ((const float4*)g_m)[mi];
    const float4 ms = ((const float4*)g_m)[mi + NB * NP / 4];
    const float4 zo = ((const float4*)g_z)[mi];
    const float4 zs = ((const float4*)g_z)[mi + NB * NP / 4];

    float4 r;
    {
        float had = __expf((a.x - mo.x) + (bb.x - ms.x)) / (zo.x * zs.x);
        r.x = (fo.x * had) * (fs.x * had);
    }
    {
        float had = __expf((a.y - mo.y) + (bb.y - ms.y)) / (zo.y * zs.y);
        r.y = (fo.y * had) * (fs.y * had);
    }
    {
        float had = __expf((a.z - mo.z) + (bb.z - ms.z)) / (zo.z * zs.z);
        r.z = (fo.z * had) * (fs.z * had);
    }
    {
        float had = __expf((a.w - mo.w) + (bb.w - ms.w)) / (zo.w * zs.w);
        r.w = (fo.w * had) * (fs.w * had);
    }
    ((float4*)out)[t] = r;
}

// ============================================================================
extern "C" void kernel_launch(void* const* d_in, const int* in_sizes, int n_in,
                              void* d_out, int out_size)
{
    const float* opt = (const float*)d_in[0];
    const float* sar = (const float*)d_in[1];
    const float* Wo  = (const float*)d_in[2];
    const float* Ws  = (const float*)d_in[3];

    k1_gemm<<<dim3(NP / 128, NC / 128, 16), 256>>>(opt, sar, Wo, Ws);
    k2_gram<<<2 * NB * NC, 256>>>();
    k3_stats<<<NB * 64, 256>>>();
    k4_final<<<(2 * (int)(BR_STRIDE / 4) / 2) / 256, 256>>>((float*)d_out);
}

// round 3
// speedup vs baseline: 3.1432x; 3.1432x over previous
#include <cuda_runtime.h>
#include <cuda_bf16.h>
#include <cstdint>

// Problem: B=8, C=512, H=W=64, P=H*W=4096
// out[b,c,h,w] = f_opt*f_sar*had^2, had = softmax_c(S_opt)*softmax_c(S_sar)
// f = W @ x (per-pixel channel mix), S[b,c] = f_bc^T f_bc (64x64)
//
// NOTE: harness compiles via virtual arch compute_103 => no tcgen05/TMEM.
// Tensor path = mma.sync HMMA (sm_80+ PTX) with bf16 split-3 for accuracy.

#define NB 8
#define NC 512
#define NP 4096
#define BR_STRIDE ((size_t)NB * NC * NP)   // floats per branch

// ---------------- scratch (static device arrays) ----------------
__device__ __align__(256) float g_f[2ull * NB * NC * NP];      // 134 MB fp32 f
__device__ __align__(256) float g_S[2ull * NB * NC * NP];      // 134 MB gram
__device__ float g_M[NB * NP];                                 // mo+ms per (b,i,j)
__device__ float g_R[NB * NP];                                 // 1/(zo*zs)
// bf16-split transposed X: layout per z: [pixel 4096][channel 512]
__device__ __align__(256) __nv_bfloat16 g_xh[2ull * NB * NP * NC];
__device__ __align__(256) __nv_bfloat16 g_xl[2ull * NB * NP * NC];
__device__ __align__(256) __nv_bfloat16 g_wh[2 * NC * NC];
__device__ __align__(256) __nv_bfloat16 g_wl[2 * NC * NC];

// ---------------- helpers ----------------
__device__ __forceinline__ uint32_t smem_u32(const void* p) {
    uint32_t a;
    asm("{ .reg .u64 t; cvta.to.shared.u64 t, %1; cvt.u32.u64 %0, t; }" : "=r"(a) : "l"(p));
    return a;
}
#define SWZ128(o) ((o) ^ (((o) >> 3) & 0x70))

#define CPA(s, g) asm volatile("cp.async.cg.shared.global [%0], [%1], 16;" :: "r"(s), "l"(g))
#define CPC()     asm volatile("cp.async.commit_group;" ::: "memory")
#define CPW(n)    asm volatile("cp.async.wait_group %0;" :: "n"(n) : "memory")

#define LDSM4(r, a) \
    asm volatile("ldmatrix.sync.aligned.m8n8.x4.shared.b16 {%0,%1,%2,%3}, [%4];" \
        : "=r"((r)[0]), "=r"((r)[1]), "=r"((r)[2]), "=r"((r)[3]) : "r"(a))

#define MMA(c, a, b0, b1) \
    asm volatile("mma.sync.aligned.m16n8k16.row.col.f32.bf16.bf16.f32 " \
        "{%0,%1,%2,%3},{%4,%5,%6,%7},{%8,%9},{%0,%1,%2,%3};" \
        : "+f"((c)[0]), "+f"((c)[1]), "+f"((c)[2]), "+f"((c)[3]) \
        : "r"((a)[0]), "r"((a)[1]), "r"((a)[2]), "r"((a)[3]), "r"(b0), "r"(b1))

// ---- packed f32x2 helpers (for k2 gram) ----
__device__ __forceinline__ unsigned long long pk2(float x, float y) {
    unsigned long long r;
    asm("mov.b64 %0, {%1,%2};" : "=l"(r) : "f"(x), "f"(y));
    return r;
}
__device__ __forceinline__ void fma2(unsigned long long& d, unsigned long long a, unsigned long long b) {
    asm("fma.rn.f32x2 %0, %1, %2, %0;" : "+l"(d) : "l"(a), "l"(b));
}
__device__ __forceinline__ float2 up2(unsigned long long v) {
    float2 r;
    asm("mov.b64 {%0,%1}, %2;" : "=f"(r.x), "=f"(r.y) : "l"(v));
    return r;
}

// ============================================================================
// k0w: split W fp32 -> (hi, lo) bf16, same [out_c, in_c] layout
// ============================================================================
__global__ __launch_bounds__(256) void k0w(const float* __restrict__ Wo,
                                           const float* __restrict__ Ws)
{
    const int mtx = blockIdx.y;
    const float* src = mtx ? Ws : Wo;
    const int i4 = blockIdx.x * 256 + threadIdx.x;   // float4 index, 65536 total
    float4 v = ((const float4*)src)[i4];
    __nv_bfloat16 hx = __float2bfloat16(v.x), hy = __float2bfloat16(v.y);
    __nv_bfloat16 hz = __float2bfloat16(v.z), hw = __float2bfloat16(v.w);
    __nv_bfloat162* oh = (__nv_bfloat162*)(g_wh + (size_t)mtx * NC * NC);
    __nv_bfloat162* ol = (__nv_bfloat162*)(g_wl + (size_t)mtx * NC * NC);
    oh[i4 * 2]     = __nv_bfloat162(hx, hy);
    oh[i4 * 2 + 1] = __nv_bfloat162(hz, hw);
    ol[i4 * 2]     = __nv_bfloat162(__float2bfloat16(v.x - __bfloat162float(hx)),
                                    __float2bfloat16(v.y - __bfloat162float(hy)));
    ol[i4 * 2 + 1] = __nv_bfloat162(__float2bfloat16(v.z - __bfloat162float(hz)),
                                    __float2bfloat16(v.w - __bfloat162float(hw)));
}

// ============================================================================
// k0x: transpose + split X: [c 512][p 4096] fp32 -> Xt hi/lo [p 4096][c 512] bf16
// ============================================================================
__global__ __launch_bounds__(256) void k0x(const float* __restrict__ opt,
                                           const float* __restrict__ sar)
{
    const int z = blockIdx.z;
    const int br = z >> 3, b = z & 7;
    const float* X = (br ? sar : opt) + (size_t)b * NC * NP;
    const int p0 = blockIdx.x * 64, c0 = blockIdx.y * 64;
    const int tid = threadIdx.x;

    __shared__ float t[64][65];
#pragma unroll
    for (int it = 0; it < 4; it++) {
        int f4 = tid + it * 256;
        int r = f4 >> 4, q = f4 & 15;
        float4 v = *(const float4*)(X + (size_t)(c0 + r) * NP + p0 + q * 4);
        t[r][q * 4 + 0] = v.x; t[r][q * 4 + 1] = v.y;
        t[r][q * 4 + 2] = v.z; t[r][q * 4 + 3] = v.w;
    }
    __syncthreads();

#pragma unroll
    for (int it = 0; it < 8; it++) {
        int u = tid + it * 256;            // [0, 2048)
        int pr = u >> 5, c2 = u & 31;
        int c = c2 * 2;
        float v0 = t[c][pr], v1 = t[c + 1][pr];
        __nv_bfloat16 h0 = __float2bfloat16(v0), h1 = __float2bfloat16(v1);
        size_t idx2 = ((size_t)z * NP * NC + (size_t)(p0 + pr) * NC + (c0 + c)) >> 1;
        ((__nv_bfloat162*)g_xh)[idx2] = __nv_bfloat162(h0, h1);
        ((__nv_bfloat162*)g_xl)[idx2] =
            __nv_bfloat162(__float2bfloat16(v0 - __bfloat162float(h0)),
                           __float2bfloat16(v1 - __bfloat162float(h1)));
    }
}

// ============================================================================
// k1: HMMA split-3 GEMM.  f[z] (512 x 4096) = W'[br] (512x512) @ X[z] (512x4096)
// A = W hi/lo [m 512][k 512] bf16 row-major. B = Xt hi/lo [n 4096][k 512] (.col).
// CTA 256 thr, tile M=128 N=128, K-chunk 64, double-buffered cp.async.
// Warp (2m x 4n): 64x32. mma.m16n8k16. acc fp32.
// grid (32 ntile, 4 mtile, 16 z)
// ============================================================================
#define K1_STAGE 65536                 // Ah 16K | Al 16K | Bh 16K | Bl 16K
#define K1_SMEM  (2 * K1_STAGE)

__global__ __launch_bounds__(256) void k1_hmma()
{
    extern __shared__ char smem[];
    const uint32_t sb = smem_u32(smem);
    const int tid = threadIdx.x;
    const int l = tid & 31, wid = tid >> 5;
    const int mwarp = wid >> 2, nwarp = wid & 3;
    const int z = blockIdx.z, br = z >> 3;
    const int m0 = blockIdx.y * 128;
    const int n0 = blockIdx.x * 128;

    const __nv_bfloat16* gAh = g_wh + (size_t)br * NC * NC;
    const __nv_bfloat16* gAl = g_wl + (size_t)br * NC * NC;
    const __nv_bfloat16* gBh = g_xh + (size_t)z * NP * NC;
    const __nv_bfloat16* gBl = g_xl + (size_t)z * NP * NC;

    float acc[4][4][4];
#pragma unroll
    for (int mf = 0; mf < 4; mf++)
#pragma unroll
        for (int nf = 0; nf < 4; nf++)
#pragma unroll
            for (int q = 0; q < 4; q++) acc[mf][nf][q] = 0.f;

    // per-thread load slots: id = tid + it*256, r = id>>3 (row), q = id&7 (16B chunk)
    const int lr = tid >> 3, lq = tid & 7;

#define K1_LOAD(kt, s) do {                                                        \
    uint32_t sbase = sb + (s) * K1_STAGE;                                          \
    _Pragma("unroll")                                                              \
    for (int it = 0; it < 4; it++) {                                               \
        int r = lr + it * 32;                                                      \
        uint32_t soff = SWZ128(r * 128 + lq * 16);                                 \
        size_t go = (size_t)r * NC + (kt) * 64 + lq * 8;                           \
        CPA(sbase + soff,         gAh + (size_t)m0 * NC + go);                     \
        CPA(sbase + 16384 + soff, gAl + (size_t)m0 * NC + go);                     \
        CPA(sbase + 32768 + soff, gBh + (size_t)n0 * NC + go);                     \
        CPA(sbase + 49152 + soff, gBl + (size_t)n0 * NC + go);                     \
    }                                                                              \
    CPC();                                                                         \
} while (0)

    K1_LOAD(0, 0);

    for (int kt = 0; kt < 8; kt++) {
        const int s = kt & 1;
        if (kt < 7) { K1_LOAD(kt + 1, s ^ 1); CPW(1); }
        else        { CPW(0); }
        __syncthreads();

        const uint32_t sA  = sb + s * K1_STAGE;
        const uint32_t sAl = sA + 16384;
        const uint32_t sB  = sA + 32768;
        const uint32_t sBl = sA + 49152;

#pragma unroll
        for (int ks = 0; ks < 4; ks++) {
            uint32_t ah[4][4], al[4][4], bh[8], bl[8];
#pragma unroll
            for (int mf = 0; mf < 4; mf++) {
                uint32_t off = (uint32_t)(mwarp * 64 + mf * 16 + (l & 15)) * 128
                             + (l >> 4) * 16 + ks * 32;
                uint32_t so = SWZ128(off);
                LDSM4(ah[mf], sA + so);
                LDSM4(al[mf], sAl + so);
            }
#pragma unroll
            for (int nf2 = 0; nf2 < 2; nf2++) {
                uint32_t off = (uint32_t)(nwarp * 32 + nf2 * 16 + (l & 7) + ((l >> 4) << 3)) * 128
                             + ((l >> 3) & 1) * 16 + ks * 32;
                uint32_t so = SWZ128(off);
                LDSM4(&bh[nf2 * 4], sB + so);
                LDSM4(&bl[nf2 * 4], sBl + so);
            }
#pragma unroll
            for (int mf = 0; mf < 4; mf++)
#pragma unroll
                for (int nf = 0; nf < 4; nf++) {
                    const int bi = (nf >> 1) * 4 + (nf & 1) * 2;
                    MMA(acc[mf][nf], ah[mf], bh[bi], bh[bi + 1]);   // hi*hi
                    MMA(acc[mf][nf], al[mf], bh[bi], bh[bi + 1]);   // lo*hi
                    MMA(acc[mf][nf], ah[mf], bl[bi], bl[bi + 1]);   // hi*lo
                }
        }
        __syncthreads();
    }

    // epilogue: direct float2 stores (each quad covers an aligned 32B sector)
    float* dst = g_f + (size_t)z * NC * NP;
    const int rbase = m0 + mwarp * 64 + (l >> 2);
    const int cbase = n0 + nwarp * 32 + (l & 3) * 2;
#pragma unroll
    for (int mf = 0; mf < 4; mf++)
#pragma unroll
        for (int nf = 0; nf < 4; nf++) {
            *(float2*)(dst + (size_t)(rbase + mf * 16) * NP + cbase + nf * 8)
                = make_float2(acc[mf][nf][0], acc[mf][nf][1]);
            *(float2*)(dst + (size_t)(rbase + mf * 16 + 8) * NP + cbase + nf * 8)
                = make_float2(acc[mf][nf][2], acc[mf][nf][3]);
        }
}

// ============================================================================
// k2: S = F^T F per (br,b,c), F is 64x64. 8192 blocks, 256 threads. f32x2 FMA.
// ============================================================================
__global__ __launch_bounds__(256) void k2_gram()
{
    const int blk = blockIdx.x;
    const float* F = g_f + (size_t)blk * NP;
    float* S = g_S + (size_t)blk * NP;

    __shared__ float Fs[64][64];
    const int tid = threadIdx.x;
#pragma unroll
    for (int it = 0; it < 4; it++)
        ((float4*)&Fs[0][0])[tid + it * 256] = ((const float4*)F)[tid + it * 256];
    __syncthreads();

    const int tj = tid & 15, ti = tid >> 4;
    unsigned long long acc[2][4];
#pragma unroll
    for (int p = 0; p < 2; p++)
#pragma unroll
        for (int j = 0; j < 4; j++) acc[p][j] = 0ull;

#pragma unroll 16
    for (int h = 0; h < 64; h++) {
        unsigned long long a0 = *(const unsigned long long*)&Fs[h][ti * 4];
        unsigned long long a1 = *(const unsigned long long*)&Fs[h][ti * 4 + 2];
        float4 bv = *(const float4*)&Fs[h][tj * 4];
        unsigned long long s0 = pk2(bv.x, bv.x), s1 = pk2(bv.y, bv.y);
        unsigned long long s2 = pk2(bv.z, bv.z), s3 = pk2(bv.w, bv.w);
        fma2(acc[0][0], a0, s0); fma2(acc[0][1], a0, s1);
        fma2(acc[0][2], a0, s2); fma2(acc[0][3], a0, s3);
        fma2(acc[1][0], a1, s0); fma2(acc[1][1], a1, s1);
        fma2(acc[1][2], a1, s2); fma2(acc[1][3], a1, s3);
    }

#pragma unroll
    for (int p = 0; p < 2; p++) {
        float2 v0 = up2(acc[p][0]), v1 = up2(acc[p][1]);
        float2 v2 = up2(acc[p][2]), v3 = up2(acc[p][3]);
        *(float4*)&S[(ti * 4 + p * 2) * 64 + tj * 4]     = make_float4(v0.x, v1.x, v2.x, v3.x);
        *(float4*)&S[(ti * 4 + p * 2 + 1) * 64 + tj * 4] = make_float4(v0.y, v1.y, v2.y, v3.y);
    }
}

// ============================================================================
// k3: softmax stats over channel axis, both branches; emits combined M, R.
// ============================================================================
__global__ __launch_bounds__(256) void k3_stats()
{
    const int blk = blockIdx.x;
    const int b = blk >> 6, i = blk & 63;
    const int tid = threadIdx.x, j = tid & 63, cg = tid >> 6;

    const float* So = g_S + (size_t)b * NC * NP + i * 64 + j;
    const float* Ss = So + BR_STRIDE;

    float mo = -1e30f, zo = 0.f, ms = -1e30f, zs = 0.f;
    for (int c = cg * 128; c < cg * 128 + 128; c++) {
        float v = So[(size_t)c * NP];
        if (v > mo) { zo = zo * __expf(mo - v) + 1.f; mo = v; }
        else        { zo += __expf(v - mo); }
        float w = Ss[(size_t)c * NP];
        if (w > ms) { zs = zs * __expf(ms - w) + 1.f; ms = w; }
        else        { zs += __expf(w - ms); }
    }

    __shared__ float shm[2][4][64], shz[2][4][64];
    shm[0][cg][j] = mo; shz[0][cg][j] = zo;
    shm[1][cg][j] = ms; shz[1][cg][j] = zs;
    __syncthreads();

    if (cg == 0) {
        float Mo = shm[0][0][j], Ms = shm[1][0][j];
#pragma unroll
        for (int q = 1; q < 4; q++) {
            Mo = fmaxf(Mo, shm[0][q][j]);
            Ms = fmaxf(Ms, shm[1][q][j]);
        }
        float Zo = 0.f, Zs = 0.f;
#pragma unroll
        for (int q = 0; q < 4; q++) {
            Zo += shz[0][q][j] * __expf(shm[0][q][j] - Mo);
            Zs += shz[1][q][j] * __expf(shm[1][q][j] - Ms);
        }
        const int idx = b * NP + i * 64 + j;
        g_M[idx] = Mo + Ms;
        g_R[idx] = 1.0f / (Zo * Zs);
    }
}

// ============================================================================
// k4: out = f_opt*f_sar*had^2, had = exp(So+Ss-M)*R
// ============================================================================
__global__ __launch_bounds__(256) void k4_final(float* __restrict__ out)
{
    const int t = blockIdx.x * 256 + threadIdx.x;
    const int j4 = t & 15;
    const int i = (t >> 4) & 63;
    const int b = t >> 19;

    const float4 a  = ((const float4*)g_S)[t];
    const float4 bb = ((const float4*)g_S)[t + (int)(BR_STRIDE / 4)];
    const float4 fo = ((const float4*)g_f)[t];
    const float4 fs = ((const float4*)g_f)[t + (int)(BR_STRIDE / 4)];

    const int mi = b * (NP / 4) + i * 16 + j4;
    const float4 M4 = ((const float4*)g_M)[mi];
    const float4 R4 = ((const float4*)g_R)[mi];

    float4 r;
    { float had = __expf(a.x + bb.x - M4.x) * R4.x; r.x = (fo.x * fs.x) * (had * had); }
    { float had = __expf(a.y + bb.y - M4.y) * R4.y; r.y = (fo.y * fs.y) * (had * had); }
    { float had = __expf(a.z + bb.z - M4.z) * R4.z; r.z = (fo.z * fs.z) * (had * had); }
    { float had = __expf(a.w + bb.w - M4.w) * R4.w; r.w = (fo.w * fs.w) * (had * had); }
    ((float4*)out)[t] = r;
}

// ============================================================================
extern "C" void kernel_launch(void* const* d_in, const int* in_sizes, int n_in,
                              void* d_out, int out_size)
{
    const float* opt = (const float*)d_in[0];
    const float* sar = (const float*)d_in[1];
    const float* Wo  = (const float*)d_in[2];
    const float* Ws  = (const float*)d_in[3];

    cudaFuncSetAttribute(k1_hmma, cudaFuncAttributeMaxDynamicSharedMemorySize, K1_SMEM);

    k0w<<<dim3(256, 2), 256>>>(Wo, Ws);
    k0x<<<dim3(64, 8, 16), 256>>>(opt, sar);
    k1_hmma<<<dim3(32, 4, 16), 256, K1_SMEM>>>();
    k2_gram<<<2 * NB * NC, 256>>>();
    k3_stats<<<NB * 64, 256>>>();
    k4_final<<<16384, 256>>>((float*)d_out);
}

// round 4
// speedup vs baseline: 3.4776x; 1.1064x over previous
#include <cuda_runtime.h>
#include <cuda_bf16.h>
#include <cstdint>

// Problem: B=8, C=512, H=W=64, P=H*W=4096
// out[b,c,h,w] = f_opt*f_sar*had^2, had = softmax_c(S_opt)*softmax_c(S_sar)
// f = W @ x (per-pixel channel mix), S[b,c] = f_bc^T f_bc (64x64)
//
// NOTE: harness compiles via virtual arch compute_103 => no tcgen05/TMEM.
// Tensor path = mma.sync HMMA (sm_80+ PTX) with bf16 split-3 for accuracy.

#define NB 8
#define NC 512
#define NP 4096
#define BR_STRIDE ((size_t)NB * NC * NP)   // floats per branch

// ---------------- scratch (static device arrays) ----------------
__device__ __align__(256) float g_f[2ull * NB * NC * NP];      // 134 MB fp32 f
__device__ __align__(256) float g_S[2ull * NB * NC * NP];      // 134 MB gram
__device__ float g_M[NB * NP];                                 // mo+ms per (b,i,j)
__device__ float g_R[NB * NP];                                 // 1/(zo*zs)
// bf16-split transposed X: layout per z: [pixel 4096][channel 512]
__device__ __align__(256) __nv_bfloat16 g_xh[2ull * NB * NP * NC];
__device__ __align__(256) __nv_bfloat16 g_xl[2ull * NB * NP * NC];
__device__ __align__(256) __nv_bfloat16 g_wh[2 * NC * NC];
__device__ __align__(256) __nv_bfloat16 g_wl[2 * NC * NC];

// ---------------- helpers ----------------
__device__ __forceinline__ uint32_t smem_u32(const void* p) {
    uint32_t a;
    asm("{ .reg .u64 t; cvta.to.shared.u64 t, %1; cvt.u32.u64 %0, t; }" : "=r"(a) : "l"(p));
    return a;
}
#define SWZ128(o) ((o) ^ (((o) >> 3) & 0x70))

#define CPA(s, g) asm volatile("cp.async.cg.shared.global [%0], [%1], 16;" :: "r"(s), "l"(g))
#define CPC()     asm volatile("cp.async.commit_group;" ::: "memory")
#define CPW(n)    asm volatile("cp.async.wait_group %0;" :: "n"(n) : "memory")

#define LDSM4(r, a) \
    asm volatile("ldmatrix.sync.aligned.m8n8.x4.shared.b16 {%0,%1,%2,%3}, [%4];" \
        : "=r"((r)[0]), "=r"((r)[1]), "=r"((r)[2]), "=r"((r)[3]) : "r"(a))

#define LDSM4T(r, a) \
    asm volatile("ldmatrix.sync.aligned.m8n8.x4.trans.shared.b16 {%0,%1,%2,%3}, [%4];" \
        : "=r"((r)[0]), "=r"((r)[1]), "=r"((r)[2]), "=r"((r)[3]) : "r"(a))

#define MMA(c, a, b0, b1) \
    asm volatile("mma.sync.aligned.m16n8k16.row.col.f32.bf16.bf16.f32 " \
        "{%0,%1,%2,%3},{%4,%5,%6,%7},{%8,%9},{%0,%1,%2,%3};" \
        : "+f"((c)[0]), "+f"((c)[1]), "+f"((c)[2]), "+f"((c)[3]) \
        : "r"((a)[0]), "r"((a)[1]), "r"((a)[2]), "r"((a)[3]), "r"(b0), "r"(b1))

// ============================================================================
// k0w: split W fp32 -> (hi, lo) bf16, same [out_c, in_c] layout
// ============================================================================
__global__ __launch_bounds__(256) void k0w(const float* __restrict__ Wo,
                                           const float* __restrict__ Ws)
{
    const int mtx = blockIdx.y;
    const float* src = mtx ? Ws : Wo;
    const int i4 = blockIdx.x * 256 + threadIdx.x;   // float4 index, 65536 total
    float4 v = ((const float4*)src)[i4];
    __nv_bfloat16 hx = __float2bfloat16(v.x), hy = __float2bfloat16(v.y);
    __nv_bfloat16 hz = __float2bfloat16(v.z), hw = __float2bfloat16(v.w);
    __nv_bfloat162* oh = (__nv_bfloat162*)(g_wh + (size_t)mtx * NC * NC);
    __nv_bfloat162* ol = (__nv_bfloat162*)(g_wl + (size_t)mtx * NC * NC);
    oh[i4 * 2]     = __nv_bfloat162(hx, hy);
    oh[i4 * 2 + 1] = __nv_bfloat162(hz, hw);
    ol[i4 * 2]     = __nv_bfloat162(__float2bfloat16(v.x - __bfloat162float(hx)),
                                    __float2bfloat16(v.y - __bfloat162float(hy)));
    ol[i4 * 2 + 1] = __nv_bfloat162(__float2bfloat16(v.z - __bfloat162float(hz)),
                                    __float2bfloat16(v.w - __bfloat162float(hw)));
}

// ============================================================================
// k0x: transpose + split X: [c 512][p 4096] fp32 -> Xt hi/lo [p 4096][c 512] bf16
// ============================================================================
__global__ __launch_bounds__(256) void k0x(const float* __restrict__ opt,
                                           const float* __restrict__ sar)
{
    const int z = blockIdx.z;
    const int br = z >> 3, b = z & 7;
    const float* X = (br ? sar : opt) + (size_t)b * NC * NP;
    const int p0 = blockIdx.x * 64, c0 = blockIdx.y * 64;
    const int tid = threadIdx.x;

    __shared__ float t[64][65];
#pragma unroll
    for (int it = 0; it < 4; it++) {
        int f4 = tid + it * 256;
        int r = f4 >> 4, q = f4 & 15;
        float4 v = *(const float4*)(X + (size_t)(c0 + r) * NP + p0 + q * 4);
        t[r][q * 4 + 0] = v.x; t[r][q * 4 + 1] = v.y;
        t[r][q * 4 + 2] = v.z; t[r][q * 4 + 3] = v.w;
    }
    __syncthreads();

#pragma unroll
    for (int it = 0; it < 8; it++) {
        int u = tid + it * 256;            // [0, 2048)
        int pr = u >> 5, c2 = u & 31;
        int c = c2 * 2;
        float v0 = t[c][pr], v1 = t[c + 1][pr];
        __nv_bfloat16 h0 = __float2bfloat16(v0), h1 = __float2bfloat16(v1);
        size_t idx2 = ((size_t)z * NP * NC + (size_t)(p0 + pr) * NC + (c0 + c)) >> 1;
        ((__nv_bfloat162*)g_xh)[idx2] = __nv_bfloat162(h0, h1);
        ((__nv_bfloat162*)g_xl)[idx2] =
            __nv_bfloat162(__float2bfloat16(v0 - __bfloat162float(h0)),
                           __float2bfloat16(v1 - __bfloat162float(h1)));
    }
}

// ============================================================================
// k1: HMMA split-3 GEMM.  f[z] (512 x 4096) = W'[br] (512x512) @ X[z] (512x4096)
// A = W hi/lo [m 512][k 512] bf16 row-major. B = Xt hi/lo [n 4096][k 512] (.col).
// CTA 256 thr, tile M=128 N=128, K-chunk 64, double-buffered cp.async.
// ============================================================================
#define K1_STAGE 65536                 // Ah 16K | Al 16K | Bh 16K | Bl 16K
#define K1_SMEM  (2 * K1_STAGE)

__global__ __launch_bounds__(256) void k1_hmma()
{
    extern __shared__ char smem[];
    const uint32_t sb = smem_u32(smem);
    const int tid = threadIdx.x;
    const int l = tid & 31, wid = tid >> 5;
    const int mwarp = wid >> 2, nwarp = wid & 3;
    const int z = blockIdx.z, br = z >> 3;
    const int m0 = blockIdx.y * 128;
    const int n0 = blockIdx.x * 128;

    const __nv_bfloat16* gAh = g_wh + (size_t)br * NC * NC;
    const __nv_bfloat16* gAl = g_wl + (size_t)br * NC * NC;
    const __nv_bfloat16* gBh = g_xh + (size_t)z * NP * NC;
    const __nv_bfloat16* gBl = g_xl + (size_t)z * NP * NC;

    float acc[4][4][4];
#pragma unroll
    for (int mf = 0; mf < 4; mf++)
#pragma unroll
        for (int nf = 0; nf < 4; nf++)
#pragma unroll
            for (int q = 0; q < 4; q++) acc[mf][nf][q] = 0.f;

    const int lr = tid >> 3, lq = tid & 7;

#define K1_LOAD(kt, s) do {                                                        \
    uint32_t sbase = sb + (s) * K1_STAGE;                                          \
    _Pragma("unroll")                                                              \
    for (int it = 0; it < 4; it++) {                                               \
        int r = lr + it * 32;                                                      \
        uint32_t soff = SWZ128(r * 128 + lq * 16);                                 \
        size_t go = (size_t)r * NC + (kt) * 64 + lq * 8;                           \
        CPA(sbase + soff,         gAh + (size_t)m0 * NC + go);                     \
        CPA(sbase + 16384 + soff, gAl + (size_t)m0 * NC + go);                     \
        CPA(sbase + 32768 + soff, gBh + (size_t)n0 * NC + go);                     \
        CPA(sbase + 49152 + soff, gBl + (size_t)n0 * NC + go);                     \
    }                                                                              \
    CPC();                                                                         \
} while (0)

    K1_LOAD(0, 0);

    for (int kt = 0; kt < 8; kt++) {
        const int s = kt & 1;
        if (kt < 7) { K1_LOAD(kt + 1, s ^ 1); CPW(1); }
        else        { CPW(0); }
        __syncthreads();

        const uint32_t sA  = sb + s * K1_STAGE;
        const uint32_t sAl = sA + 16384;
        const uint32_t sB  = sA + 32768;
        const uint32_t sBl = sA + 49152;

#pragma unroll
        for (int ks = 0; ks < 4; ks++) {
            uint32_t ah[4][4], al[4][4], bh[8], bl[8];
#pragma unroll
            for (int mf = 0; mf < 4; mf++) {
                uint32_t off = (uint32_t)(mwarp * 64 + mf * 16 + (l & 15)) * 128
                             + (l >> 4) * 16 + ks * 32;
                uint32_t so = SWZ128(off);
                LDSM4(ah[mf], sA + so);
                LDSM4(al[mf], sAl + so);
            }
#pragma unroll
            for (int nf2 = 0; nf2 < 2; nf2++) {
                uint32_t off = (uint32_t)(nwarp * 32 + nf2 * 16 + (l & 7) + ((l >> 4) << 3)) * 128
                             + ((l >> 3) & 1) * 16 + ks * 32;
                uint32_t so = SWZ128(off);
                LDSM4(&bh[nf2 * 4], sB + so);
                LDSM4(&bl[nf2 * 4], sBl + so);
            }
#pragma unroll
            for (int mf = 0; mf < 4; mf++)
#pragma unroll
                for (int nf = 0; nf < 4; nf++) {
                    const int bi = (nf >> 1) * 4 + (nf & 1) * 2;
                    MMA(acc[mf][nf], ah[mf], bh[bi], bh[bi + 1]);   // hi*hi
                    MMA(acc[mf][nf], al[mf], bh[bi], bh[bi + 1]);   // lo*hi
                    MMA(acc[mf][nf], ah[mf], bl[bi], bl[bi + 1]);   // hi*lo
                }
        }
        __syncthreads();
    }

    float* dst = g_f + (size_t)z * NC * NP;
    const int rbase = m0 + mwarp * 64 + (l >> 2);
    const int cbase = n0 + nwarp * 32 + (l & 3) * 2;
#pragma unroll
    for (int mf = 0; mf < 4; mf++)
#pragma unroll
        for (int nf = 0; nf < 4; nf++) {
            *(float2*)(dst + (size_t)(rbase + mf * 16) * NP + cbase + nf * 8)
                = make_float2(acc[mf][nf][0], acc[mf][nf][1]);
            *(float2*)(dst + (size_t)(rbase + mf * 16 + 8) * NP + cbase + nf * 8)
                = make_float2(acc[mf][nf][2], acc[mf][nf][3]);
        }
}

// ============================================================================
// k2: S = F^T F per (br,b,c) via HMMA split-2x. F (fp32, 64h x 64w) is read
// directly, converted in-smem to bf16 hi/lo [h][i] K-major tiles, and both
// mma operands come from the same tiles via ldmatrix.trans.
// S ~= Fh^T Fh + Fh^T Fl + Fl^T Fh  (Fl^T Fl term ~2^-16*S, dropped)
// 8192 blocks, 128 threads (4 warps; warp w computes rows i in [w*16, w*16+16)).
// ============================================================================
__global__ __launch_bounds__(128) void k2_gram()
{
    const int blk = blockIdx.x;                       // br*4096 + b*512 + c
    const float4* F4 = (const float4*)g_f + (size_t)blk * 1024;
    float* S = g_S + (size_t)blk * NP;

    __shared__ __align__(16) __nv_bfloat16 sh[64 * 72];   // 144B rows (16B-aligned)
    __shared__ __align__(16) __nv_bfloat16 sl[64 * 72];

    const int tid = threadIdx.x;
    const int l = tid & 31, w = tid >> 5;

    // phase 1: load fp32 F, split to bf16 hi/lo in smem ([h][w] layout)
#pragma unroll
    for (int it = 0; it < 8; it++) {
        int f4 = tid + it * 128;                      // [0, 1024)
        float4 v = F4[f4];
        int r = f4 >> 4, c = (f4 & 15) * 4;
        __nv_bfloat16 hx = __float2bfloat16(v.x), hy = __float2bfloat16(v.y);
        __nv_bfloat16 hz = __float2bfloat16(v.z), hw = __float2bfloat16(v.w);
        uint32_t h01 = ((uint32_t)__bfloat16_as_ushort(hy) << 16) | __bfloat16_as_ushort(hx);
        uint32_t h23 = ((uint32_t)__bfloat16_as_ushort(hw) << 16) | __bfloat16_as_ushort(hz);
        __nv_bfloat16 lx = __float2bfloat16(v.x - __bfloat162float(hx));
        __nv_bfloat16 ly = __float2bfloat16(v.y - __bfloat162float(hy));
        __nv_bfloat16 lz = __float2bfloat16(v.z - __bfloat162float(hz));
        __nv_bfloat16 lw = __float2bfloat16(v.w - __bfloat162float(hw));
        uint32_t l01 = ((uint32_t)__bfloat16_as_ushort(ly) << 16) | __bfloat16_as_ushort(lx);
        uint32_t l23 = ((uint32_t)__bfloat16_as_ushort(lw) << 16) | __bfloat16_as_ushort(lz);
        *(uint2*)&sh[r * 72 + c] = make_uint2(h01, h23);
        *(uint2*)&sl[r * 72 + c] = make_uint2(l01, l23);
    }
    __syncthreads();

    const uint32_t shb = smem_u32(sh), slb = smem_u32(sl);
    const int i0 = w * 16;
    const int g = l >> 3;

    float acc[8][4];
#pragma unroll
    for (int jt = 0; jt < 8; jt++)
#pragma unroll
        for (int q = 0; q < 4; q++) acc[jt][q] = 0.f;

#pragma unroll
    for (int ks = 0; ks < 4; ks++) {
        uint32_t ah[4], al[4];
        {
            // A (m16k16, rows i0..i0+15): trans-load from [k][m] tiles
            int row = ks * 16 + (g >> 1) * 8 + (l & 7);
            int col = i0 + (g & 1) * 8;
            uint32_t addr = (uint32_t)(row * 144 + col * 2);
            LDSM4T(ah, shb + addr);
            LDSM4T(al, slb + addr);
        }
        uint32_t bh[16], bl[16];
#pragma unroll
        for (int jt2 = 0; jt2 < 4; jt2++) {
            // B (two n8k16 tiles per x4): trans-load from [k][n] tiles
            int row = ks * 16 + (g & 1) * 8 + (l & 7);
            int col = jt2 * 16 + (g >> 1) * 8;
            uint32_t addr = (uint32_t)(row * 144 + col * 2);
            LDSM4T(&bh[jt2 * 4], shb + addr);
            LDSM4T(&bl[jt2 * 4], slb + addr);
        }
#pragma unroll
        for (int jt = 0; jt < 8; jt++) {
            int bi = (jt >> 1) * 4 + (jt & 1) * 2;
            MMA(acc[jt], ah, bh[bi], bh[bi + 1]);     // hi*hi
            MMA(acc[jt], al, bh[bi], bh[bi + 1]);     // lo*hi
            MMA(acc[jt], ah, bl[bi], bl[bi + 1]);     // hi*lo
        }
    }

    const int ir = i0 + (l >> 2);
    const int jc = (l & 3) * 2;
#pragma unroll
    for (int jt = 0; jt < 8; jt++) {
        *(float2*)&S[ir * 64 + jt * 8 + jc]       = make_float2(acc[jt][0], acc[jt][1]);
        *(float2*)&S[(ir + 8) * 64 + jt * 8 + jc] = make_float2(acc[jt][2], acc[jt][3]);
    }
}

// ============================================================================
// k3: softmax stats over channel axis, both branches; emits combined M, R.
// ============================================================================
__global__ __launch_bounds__(256) void k3_stats()
{
    const int blk = blockIdx.x;
    const int b = blk >> 6, i = blk & 63;
    const int tid = threadIdx.x, j = tid & 63, cg = tid >> 6;

    const float* So = g_S + (size_t)b * NC * NP + i * 64 + j;
    const float* Ss = So + BR_STRIDE;

    float mo = -1e30f, zo = 0.f, ms = -1e30f, zs = 0.f;
    for (int c = cg * 128; c < cg * 128 + 128; c++) {
        float v = So[(size_t)c * NP];
        if (v > mo) { zo = zo * __expf(mo - v) + 1.f; mo = v; }
        else        { zo += __expf(v - mo); }
        float w = Ss[(size_t)c * NP];
        if (w > ms) { zs = zs * __expf(ms - w) + 1.f; ms = w; }
        else        { zs += __expf(w - ms); }
    }

    __shared__ float shm[2][4][64], shz[2][4][64];
    shm[0][cg][j] = mo; shz[0][cg][j] = zo;
    shm[1][cg][j] = ms; shz[1][cg][j] = zs;
    __syncthreads();

    if (cg == 0) {
        float Mo = shm[0][0][j], Ms = shm[1][0][j];
#pragma unroll
        for (int q = 1; q < 4; q++) {
            Mo = fmaxf(Mo, shm[0][q][j]);
            Ms = fmaxf(Ms, shm[1][q][j]);
        }
        float Zo = 0.f, Zs = 0.f;
#pragma unroll
        for (int q = 0; q < 4; q++) {
            Zo += shz[0][q][j] * __expf(shm[0][q][j] - Mo);
            Zs += shz[1][q][j] * __expf(shm[1][q][j] - Ms);
        }
        const int idx = b * NP + i * 64 + j;
        g_M[idx] = Mo + Ms;
        g_R[idx] = 1.0f / (Zo * Zs);
    }
}

// ============================================================================
// k4: out = f_opt*f_sar*had^2, had = exp(So+Ss-M)*R
// ============================================================================
__global__ __launch_bounds__(256) void k4_final(float* __restrict__ out)
{
    const int t = blockIdx.x * 256 + threadIdx.x;
    const int j4 = t & 15;
    const int i = (t >> 4) & 63;
    const int b = t >> 19;

    const float4 a  = ((const float4*)g_S)[t];
    const float4 bb = ((const float4*)g_S)[t + (int)(BR_STRIDE / 4)];
    const float4 fo = ((const float4*)g_f)[t];
    const float4 fs = ((const float4*)g_f)[t + (int)(BR_STRIDE / 4)];

    const int mi = b * (NP / 4) + i * 16 + j4;
    const float4 M4 = ((const float4*)g_M)[mi];
    const float4 R4 = ((const float4*)g_R)[mi];

    float4 r;
    { float had = __expf(a.x + bb.x - M4.x) * R4.x; r.x = (fo.x * fs.x) * (had * had); }
    { float had = __expf(a.y + bb.y - M4.y) * R4.y; r.y = (fo.y * fs.y) * (had * had); }
    { float had = __expf(a.z + bb.z - M4.z) * R4.z; r.z = (fo.z * fs.z) * (had * had); }
    { float had = __expf(a.w + bb.w - M4.w) * R4.w; r.w = (fo.w * fs.w) * (had * had); }
    ((float4*)out)[t] = r;
}

// ============================================================================
extern "C" void kernel_launch(void* const* d_in, const int* in_sizes, int n_in,
                              void* d_out, int out_size)
{
    const float* opt = (const float*)d_in[0];
    const float* sar = (const float*)d_in[1];
    const float* Wo  = (const float*)d_in[2];
    const float* Ws  = (const float*)d_in[3];

    cudaFuncSetAttribute(k1_hmma, cudaFuncAttributeMaxDynamicSharedMemorySize, K1_SMEM);

    k0w<<<dim3(256, 2), 256>>>(Wo, Ws);
    k0x<<<dim3(64, 8, 16), 256>>>(opt, sar);
    k1_hmma<<<dim3(32, 4, 16), 256, K1_SMEM>>>();
    k2_gram<<<2 * NB * NC, 128>>>();
    k3_stats<<<NB * 64, 256>>>();
    k4_final<<<16384, 256>>>((float*)d_out);
}